// round 4
// baseline (speedup 1.0000x reference)
#include <cuda_runtime.h>
#include <cstdint>

// ---------------------------------------------------------------------------
// Problem constants
// ---------------------------------------------------------------------------
#define BS      2
#define SEQ     4096
#define DMODEL  768
#define HEADS   12
#define DK      64
#define MROWS   (BS * SEQ)          // 8192

// ---------------------------------------------------------------------------
// Scratch (device globals; no cudaMalloc allowed)
// ---------------------------------------------------------------------------
__device__ float g_Qp[MROWS * DMODEL];
__device__ float g_Kp[MROWS * DMODEL];
__device__ float g_Vt[(size_t)BS * DMODEL * SEQ];   // [b][dmodel][seq]
__device__ float g_Ctx[MROWS * DMODEL];

// ---------------------------------------------------------------------------
// Helpers: tf32 convert + mma.sync
// ---------------------------------------------------------------------------
__device__ __forceinline__ uint32_t f2tf(float f) {
    uint32_t u;
    asm("cvt.rna.tf32.f32 %0, %1;" : "=r"(u) : "f"(f));
    return u;
}

__device__ __forceinline__ void mma8(float* d,
                                     uint32_t a0, uint32_t a1, uint32_t a2, uint32_t a3,
                                     uint32_t b0, uint32_t b1) {
    asm volatile(
        "mma.sync.aligned.m16n8k8.row.col.f32.tf32.tf32.f32 "
        "{%0,%1,%2,%3}, {%4,%5,%6,%7}, {%8,%9}, {%0,%1,%2,%3};"
        : "+f"(d[0]), "+f"(d[1]), "+f"(d[2]), "+f"(d[3])
        : "r"(a0), "r"(a1), "r"(a2), "r"(a3), "r"(b0), "r"(b1));
}

__device__ __forceinline__ void st_tf4(uint32_t* p, float4 v) {
    uint4 u;
    u.x = f2tf(v.x); u.y = f2tf(v.y); u.z = f2tf(v.z); u.w = f2tf(v.w);
    *(uint4*)p = u;
}

// ---------------------------------------------------------------------------
// GEMM: C[M,N] = A[M,K] @ B[N,K]^T + bias[N]  (round-3 proven, unchanged)
// ---------------------------------------------------------------------------
#define GBM 128
#define GBN 128
#define GBK 16
#define GLD 20

template <int TRANS>
__global__ __launch_bounds__(256, 2) void gemm_tc(
    const float* __restrict__ A, const float* __restrict__ B,
    const float* __restrict__ bias, float* __restrict__ C,
    int M, int N, int K)
{
    __shared__ uint32_t As[GBM * GLD];
    __shared__ uint32_t Bs[GBN * GLD];

    const int tid = threadIdx.x;
    const int lane = tid & 31, wid = tid >> 5;
    const int g = lane >> 2, tig = lane & 3;
    const int wm = (wid & 3) * 32, wn = (wid >> 2) * 64;
    const int row0 = blockIdx.y * GBM, col0 = blockIdx.x * GBN;

    const int r0 = tid >> 2;
    const int c4 = (tid & 3) * 4;
    const float* Aptr = A + (size_t)(row0 + r0) * K + c4;
    const float* Bptr = B + (size_t)(col0 + r0) * K + c4;

    float4 pa0 = *(const float4*)Aptr;
    float4 pa1 = *(const float4*)(Aptr + (size_t)64 * K);
    float4 pb0 = *(const float4*)Bptr;
    float4 pb1 = *(const float4*)(Bptr + (size_t)64 * K);

    float acc[2][8][4] = {};

    int k0 = 0;
    while (true) {
        __syncthreads();
        st_tf4(As + r0 * GLD + c4, pa0);
        st_tf4(As + (r0 + 64) * GLD + c4, pa1);
        st_tf4(Bs + r0 * GLD + c4, pb0);
        st_tf4(Bs + (r0 + 64) * GLD + c4, pb1);
        __syncthreads();

        k0 += GBK;
        const bool more = (k0 < K);
        if (more) {
            pa0 = *(const float4*)(Aptr + k0);
            pa1 = *(const float4*)(Aptr + (size_t)64 * K + k0);
            pb0 = *(const float4*)(Bptr + k0);
            pb1 = *(const float4*)(Bptr + (size_t)64 * K + k0);
        }

        #pragma unroll
        for (int ks = 0; ks < 2; ks++) {
            const int kk = ks * 8;
            uint32_t a[2][4];
            #pragma unroll
            for (int i = 0; i < 2; i++) {
                const int rb = wm + i * 16;
                a[i][0] = As[(rb + g) * GLD + kk + tig];
                a[i][1] = As[(rb + 8 + g) * GLD + kk + tig];
                a[i][2] = As[(rb + g) * GLD + kk + tig + 4];
                a[i][3] = As[(rb + 8 + g) * GLD + kk + tig + 4];
            }
            #pragma unroll
            for (int j = 0; j < 8; j++) {
                const int cn = wn + j * 8 + g;
                uint32_t b0 = Bs[cn * GLD + kk + tig];
                uint32_t b1 = Bs[cn * GLD + kk + tig + 4];
                mma8(acc[0][j], a[0][0], a[0][1], a[0][2], a[0][3], b0, b1);
                mma8(acc[1][j], a[1][0], a[1][1], a[1][2], a[1][3], b0, b1);
            }
        }
        if (!more) break;
    }

    #pragma unroll
    for (int i = 0; i < 2; i++) {
        const int rA = row0 + wm + i * 16 + g;
        const int rB = rA + 8;
        #pragma unroll
        for (int j = 0; j < 8; j++) {
            const int col = col0 + wn + j * 8 + 2 * tig;
            const float bx = __ldg(bias + col), by = __ldg(bias + col + 1);
            if (TRANS == 0) {
                float2 v0 = make_float2(acc[i][j][0] + bx, acc[i][j][1] + by);
                float2 v1 = make_float2(acc[i][j][2] + bx, acc[i][j][3] + by);
                *(float2*)(C + (size_t)rA * N + col) = v0;
                *(float2*)(C + (size_t)rB * N + col) = v1;
            } else {
                const int bA = rA >> 12, sA = rA & (SEQ - 1);
                const int bB = rB >> 12, sB = rB & (SEQ - 1);
                C[((size_t)bA * DMODEL + col)     * SEQ + sA] = acc[i][j][0] + bx;
                C[((size_t)bA * DMODEL + col + 1) * SEQ + sA] = acc[i][j][1] + by;
                C[((size_t)bB * DMODEL + col)     * SEQ + sB] = acc[i][j][2] + bx;
                C[((size_t)bB * DMODEL + col + 1) * SEQ + sB] = acc[i][j][3] + by;
            }
        }
    }
}

// ---------------------------------------------------------------------------
// Attention, fragment-packed smem.
// CTA = (b, h, 128-query tile), 256 threads = 8 warps x 16 q-rows.
// Smem layouts (uint32 words):
//   KPK/VPK (B-frags): unit(ks,j) stride 66: [unit*66 + lane*2 + w], w=0..1
//   QPK (A-frags, per warp): [warp*1056 + ks*132 + lane*4 + w], w=0..3
//   PPK (A-frags, per warp): [warp*1056 + ks*132 + wsel*64 + plane*2 + (w&1)]
// ---------------------------------------------------------------------------
#define KPK_OFF 0
#define VPK_OFF 4224
#define QPK_OFF 8448
#define PPK_OFF 16896
#define MSK_OFF 25344
#define ATT_WORDS (MSK_OFF + 64)
#define ATT_SMEM (ATT_WORDS * 4)    // 101632 bytes

__global__ void __launch_bounds__(256, 2)
attn_tc(const float* __restrict__ Qp, const float* __restrict__ Kp,
        const float* __restrict__ Vt, const int* __restrict__ mask,
        float* __restrict__ Ctx)
{
    extern __shared__ uint32_t sm[];
    uint32_t* KPK = sm + KPK_OFF;
    uint32_t* VPK = sm + VPK_OFF;
    uint32_t* QPK = sm + QPK_OFF;
    uint32_t* PPK = sm + PPK_OFF;
    float*    Msf = (float*)(sm + MSK_OFF);

    const int tid = threadIdx.x;
    const int lane = tid & 31, wid = tid >> 5;
    const int g = lane >> 2, tig = lane & 3;
    const int b = blockIdx.y / HEADS, h = blockIdx.y % HEADS;
    const int q0 = blockIdx.x * 128;

    // ---- stage Q once, packed A-frag layout, prescaled by 0.125 ----
    {
        const float* qg = Qp + ((size_t)(b * SEQ + q0)) * DMODEL + h * DK;
        #pragma unroll
        for (int i = 0; i < 8; i++) {
            const int r = (tid >> 4) + i * 16;       // 0..127
            const int c40 = (tid & 15) * 4;          // 0..60
            float4 v = *(const float4*)(qg + (size_t)r * DMODEL + c40);
            float vv[4] = {v.x * 0.125f, v.y * 0.125f, v.z * 0.125f, v.w * 0.125f};
            const int wb = r >> 4, rr = r & 15;
            #pragma unroll
            for (int ii = 0; ii < 4; ii++) {
                const int c = c40 + ii;
                const int ks = c >> 3;
                const int plane = (rr & 7) * 4 + (c & 3);
                const int w = (rr >> 3) + 2 * ((c >> 2) & 1);
                QPK[wb * 1056 + ks * 132 + plane * 4 + w] = f2tf(vv[ii]);
            }
        }
    }

    float o[8][4] = {};
    float l0 = 0.f, l1 = 0.f;

    const float* kg = Kp + ((size_t)b * SEQ) * DMODEL + h * DK;
    const float* vg = Vt + ((size_t)(b * DMODEL + h * DK)) * SEQ;
    const int* mg = mask + b * SEQ;

    const uint32_t* QW = QPK + wid * 1056;
    uint32_t* PW = PPK + wid * 1056;
    const uint32_t pplane1 = 4 * g + 2 * (tig & 1);       // P write plane
    const uint32_t pwsel = (tig >> 1) * 64;

    for (int kt = 0; kt < SEQ / 64; kt++) {
        const int k0 = kt * 64;
        if (kt) __syncthreads();       // prior O-phase must be done with K/V

        // ---- stage K & V tiles, lane-matched packed B-frags ----
        // warp `wid` owns j = wid; per ks: 2+2 scalar LDG + 2 conflict-free STS.64
        {
            const int rK = k0 + wid * 8 + (lane >> 2);      // key row for K
            const int dV = wid * 8 + (lane >> 2);           // d row for V
            const float* kr = kg + (size_t)rK * DMODEL + (lane & 3);
            const float* vr = vg + (size_t)dV * SEQ + k0 + (lane & 3);
            #pragma unroll
            for (int ks = 0; ks < 8; ks++) {
                uint2 pk, pv;
                pk.x = f2tf(kr[ks * 8]);
                pk.y = f2tf(kr[ks * 8 + 4]);
                pv.x = f2tf(vr[ks * 8]);
                pv.y = f2tf(vr[ks * 8 + 4]);
                *(uint2*)&KPK[(ks * 8 + wid) * 66 + lane * 2] = pk;
                *(uint2*)&VPK[(ks * 8 + wid) * 66 + lane * 2] = pv;
            }
        }
        if (tid < 64) Msf[tid] = (mg[k0 + tid] != 0) ? 1.f : 0.f;
        __syncthreads();

        // ---- S = Q K^T ----
        float s[8][4] = {};
        #pragma unroll
        for (int ks = 0; ks < 8; ks++) {
            uint4 a = *(const uint4*)&QW[ks * 132 + lane * 4];
            #pragma unroll
            for (int j = 0; j < 8; j++) {
                uint2 bb = *(const uint2*)&KPK[(ks * 8 + j) * 66 + lane * 2];
                mma8(s[j], a.x, a.y, a.z, a.w, bb.x, bb.y);
            }
        }

        // ---- softmax, write P packed in A-frag order ----
        #pragma unroll
        for (int j = 0; j < 8; j++) {
            float2 m = *(const float2*)&Msf[j * 8 + 2 * tig];
            float p0 = __expf(s[j][0]) * m.x;
            float p1 = __expf(s[j][1]) * m.y;
            float p2 = __expf(s[j][2]) * m.x;
            float p3 = __expf(s[j][3]) * m.y;
            l0 += p0 + p1;
            l1 += p2 + p3;
            uint32_t* base = PW + j * 132 + pwsel;
            uint2 u0; u0.x = f2tf(p0); u0.y = f2tf(p2);
            uint2 u1; u1.x = f2tf(p1); u1.y = f2tf(p3);
            *(uint2*)&base[pplane1 * 2] = u0;
            *(uint2*)&base[(pplane1 + 1) * 2] = u1;
        }
        __syncwarp();

        // ---- O += P V^T ----
        #pragma unroll
        for (int ks = 0; ks < 8; ks++) {
            uint2 lo = *(const uint2*)&PW[ks * 132 + lane * 2];
            uint2 hi = *(const uint2*)&PW[ks * 132 + 64 + lane * 2];
            #pragma unroll
            for (int j = 0; j < 8; j++) {
                uint2 bb = *(const uint2*)&VPK[(ks * 8 + j) * 66 + lane * 2];
                mma8(o[j], lo.x, lo.y, hi.x, hi.y, bb.x, bb.y);
            }
        }
    }

    // ---- finalize ----
    l0 += __shfl_xor_sync(0xffffffffu, l0, 1);
    l0 += __shfl_xor_sync(0xffffffffu, l0, 2);
    l1 += __shfl_xor_sync(0xffffffffu, l1, 1);
    l1 += __shfl_xor_sync(0xffffffffu, l1, 2);
    const float i0 = 1.f / l0, i1 = 1.f / l1;

    float* cg = Ctx + ((size_t)(b * SEQ + q0 + wid * 16)) * DMODEL + h * DK;
    #pragma unroll
    for (int j = 0; j < 8; j++) {
        const int col = j * 8 + 2 * tig;
        *(float2*)(cg + (size_t)g * DMODEL + col) =
            make_float2(o[j][0] * i0, o[j][1] * i0);
        *(float2*)(cg + (size_t)(8 + g) * DMODEL + col) =
            make_float2(o[j][2] * i1, o[j][3] * i1);
    }
}

// ---------------------------------------------------------------------------
// Launcher.  Inputs: q, k, v, Wq, bq, Wk, bk, Wv, bv, Wo, bo, mask
// ---------------------------------------------------------------------------
extern "C" void kernel_launch(void* const* d_in, const int* in_sizes, int n_in,
                              void* d_out, int out_size)
{
    const float* q    = (const float*)d_in[0];
    const float* k    = (const float*)d_in[1];
    const float* v    = (const float*)d_in[2];
    const float* Wq   = (const float*)d_in[3];
    const float* bq   = (const float*)d_in[4];
    const float* Wk   = (const float*)d_in[5];
    const float* bk   = (const float*)d_in[6];
    const float* Wv   = (const float*)d_in[7];
    const float* bv   = (const float*)d_in[8];
    const float* Wo   = (const float*)d_in[9];
    const float* bo   = (const float*)d_in[10];
    const int*   mask = (const int*)d_in[11];
    float* out = (float*)d_out;

    float *Qp, *Kp, *Vt, *Ctx;
    cudaGetSymbolAddress((void**)&Qp,  g_Qp);
    cudaGetSymbolAddress((void**)&Kp,  g_Kp);
    cudaGetSymbolAddress((void**)&Vt,  g_Vt);
    cudaGetSymbolAddress((void**)&Ctx, g_Ctx);

    cudaFuncSetAttribute(attn_tc, cudaFuncAttributeMaxDynamicSharedMemorySize,
                         ATT_SMEM);

    dim3 ggrid(DMODEL / GBN, MROWS / GBM);   // (6, 64)
    dim3 gblk(256);

    gemm_tc<0><<<ggrid, gblk>>>(q, Wq, bq, Qp, MROWS, DMODEL, DMODEL);
    gemm_tc<0><<<ggrid, gblk>>>(k, Wk, bk, Kp, MROWS, DMODEL, DMODEL);
    gemm_tc<1><<<ggrid, gblk>>>(v, Wv, bv, Vt, MROWS, DMODEL, DMODEL);

    dim3 agrid(SEQ / 128, BS * HEADS);       // (32, 24)
    attn_tc<<<agrid, 256, ATT_SMEM>>>(Qp, Kp, Vt, mask, Ctx);

    gemm_tc<0><<<ggrid, gblk>>>(Ctx, Wo, bo, out, MROWS, DMODEL, DMODEL);
}

// round 5
// speedup vs baseline: 1.3011x; 1.3011x over previous
#include <cuda_runtime.h>
#include <cstdint>

// ---------------------------------------------------------------------------
// Problem constants
// ---------------------------------------------------------------------------
#define BS      2
#define SEQ     4096
#define DMODEL  768
#define HEADS   12
#define DK      64
#define MROWS   (BS * SEQ)          // 8192

// ---------------------------------------------------------------------------
// Scratch (device globals; no cudaMalloc allowed)
// ---------------------------------------------------------------------------
__device__ float g_Qp[MROWS * DMODEL];
__device__ float g_Kp[MROWS * DMODEL];
__device__ float g_Vt[(size_t)BS * DMODEL * SEQ];   // [b][dmodel][seq]
__device__ float g_Ctx[MROWS * DMODEL];

// ---------------------------------------------------------------------------
// Helpers: tf32 convert + mma.sync
// ---------------------------------------------------------------------------
__device__ __forceinline__ uint32_t f2tf(float f) {
    uint32_t u;
    asm("cvt.rna.tf32.f32 %0, %1;" : "=r"(u) : "f"(f));
    return u;
}

__device__ __forceinline__ void mma8(float* d,
                                     uint32_t a0, uint32_t a1, uint32_t a2, uint32_t a3,
                                     uint32_t b0, uint32_t b1) {
    asm volatile(
        "mma.sync.aligned.m16n8k8.row.col.f32.tf32.tf32.f32 "
        "{%0,%1,%2,%3}, {%4,%5,%6,%7}, {%8,%9}, {%0,%1,%2,%3};"
        : "+f"(d[0]), "+f"(d[1]), "+f"(d[2]), "+f"(d[3])
        : "r"(a0), "r"(a1), "r"(a2), "r"(a3), "r"(b0), "r"(b1));
}

__device__ __forceinline__ void st_tf4(uint32_t* p, float4 v) {
    uint4 u;
    u.x = f2tf(v.x); u.y = f2tf(v.y); u.z = f2tf(v.z); u.w = f2tf(v.w);
    *(uint4*)p = u;
}

// ---------------------------------------------------------------------------
// GEMM: C[M,N] = A[M,K] @ B[N,K]^T + bias[N]  (round-3 proven, unchanged)
// ---------------------------------------------------------------------------
#define GBM 128
#define GBN 128
#define GBK 16
#define GLD 20

template <int TRANS>
__global__ __launch_bounds__(256, 2) void gemm_tc(
    const float* __restrict__ A, const float* __restrict__ B,
    const float* __restrict__ bias, float* __restrict__ C,
    int M, int N, int K)
{
    __shared__ uint32_t As[GBM * GLD];
    __shared__ uint32_t Bs[GBN * GLD];

    const int tid = threadIdx.x;
    const int lane = tid & 31, wid = tid >> 5;
    const int g = lane >> 2, tig = lane & 3;
    const int wm = (wid & 3) * 32, wn = (wid >> 2) * 64;
    const int row0 = blockIdx.y * GBM, col0 = blockIdx.x * GBN;

    const int r0 = tid >> 2;
    const int c4 = (tid & 3) * 4;
    const float* Aptr = A + (size_t)(row0 + r0) * K + c4;
    const float* Bptr = B + (size_t)(col0 + r0) * K + c4;

    float4 pa0 = *(const float4*)Aptr;
    float4 pa1 = *(const float4*)(Aptr + (size_t)64 * K);
    float4 pb0 = *(const float4*)Bptr;
    float4 pb1 = *(const float4*)(Bptr + (size_t)64 * K);

    float acc[2][8][4] = {};

    int k0 = 0;
    while (true) {
        __syncthreads();
        st_tf4(As + r0 * GLD + c4, pa0);
        st_tf4(As + (r0 + 64) * GLD + c4, pa1);
        st_tf4(Bs + r0 * GLD + c4, pb0);
        st_tf4(Bs + (r0 + 64) * GLD + c4, pb1);
        __syncthreads();

        k0 += GBK;
        const bool more = (k0 < K);
        if (more) {
            pa0 = *(const float4*)(Aptr + k0);
            pa1 = *(const float4*)(Aptr + (size_t)64 * K + k0);
            pb0 = *(const float4*)(Bptr + k0);
            pb1 = *(const float4*)(Bptr + (size_t)64 * K + k0);
        }

        #pragma unroll
        for (int ks = 0; ks < 2; ks++) {
            const int kk = ks * 8;
            uint32_t a[2][4];
            #pragma unroll
            for (int i = 0; i < 2; i++) {
                const int rb = wm + i * 16;
                a[i][0] = As[(rb + g) * GLD + kk + tig];
                a[i][1] = As[(rb + 8 + g) * GLD + kk + tig];
                a[i][2] = As[(rb + g) * GLD + kk + tig + 4];
                a[i][3] = As[(rb + 8 + g) * GLD + kk + tig + 4];
            }
            #pragma unroll
            for (int j = 0; j < 8; j++) {
                const int cn = wn + j * 8 + g;
                uint32_t b0 = Bs[cn * GLD + kk + tig];
                uint32_t b1 = Bs[cn * GLD + kk + tig + 4];
                mma8(acc[0][j], a[0][0], a[0][1], a[0][2], a[0][3], b0, b1);
                mma8(acc[1][j], a[1][0], a[1][1], a[1][2], a[1][3], b0, b1);
            }
        }
        if (!more) break;
    }

    #pragma unroll
    for (int i = 0; i < 2; i++) {
        const int rA = row0 + wm + i * 16 + g;
        const int rB = rA + 8;
        #pragma unroll
        for (int j = 0; j < 8; j++) {
            const int col = col0 + wn + j * 8 + 2 * tig;
            const float bx = __ldg(bias + col), by = __ldg(bias + col + 1);
            if (TRANS == 0) {
                float2 v0 = make_float2(acc[i][j][0] + bx, acc[i][j][1] + by);
                float2 v1 = make_float2(acc[i][j][2] + bx, acc[i][j][3] + by);
                *(float2*)(C + (size_t)rA * N + col) = v0;
                *(float2*)(C + (size_t)rB * N + col) = v1;
            } else {
                const int bA = rA >> 12, sA = rA & (SEQ - 1);
                const int bB = rB >> 12, sB = rB & (SEQ - 1);
                C[((size_t)bA * DMODEL + col)     * SEQ + sA] = acc[i][j][0] + bx;
                C[((size_t)bA * DMODEL + col + 1) * SEQ + sA] = acc[i][j][1] + by;
                C[((size_t)bB * DMODEL + col)     * SEQ + sB] = acc[i][j][2] + bx;
                C[((size_t)bB * DMODEL + col + 1) * SEQ + sB] = acc[i][j][3] + by;
            }
        }
    }
}

// ---------------------------------------------------------------------------
// Attention (round-3 structure + Q-in-registers + 8-warp CTA / 128 queries).
// Smem: Ks[64][ALD], Vs[64][ALD] (V as [d][key]), Ps[128][ALD], mask[64].
// Q is staged once through Ps (coalesced), its A-fragments kept in registers.
// All smem access patterns are bank-conflict-free (stride ALD=68, 68%32=4,
// bank = lane for fragment loads).
// ---------------------------------------------------------------------------
#define ALD 68
#define ATT_WORDS (2 * 64 * ALD + 128 * ALD + 64)     // 17472
#define ATT_SMEM  (ATT_WORDS * 4)                     // 69888 bytes

__global__ void __launch_bounds__(256)
attn_tc(const float* __restrict__ Qp, const float* __restrict__ Kp,
        const float* __restrict__ Vt, const int* __restrict__ mask,
        float* __restrict__ Ctx)
{
    extern __shared__ uint32_t sm[];
    uint32_t* Ks = sm;
    uint32_t* Vs = sm + 64 * ALD;
    uint32_t* Ps = sm + 2 * 64 * ALD;          // 128 rows
    float*   Msf = (float*)(sm + 2 * 64 * ALD + 128 * ALD);

    const int tid = threadIdx.x;
    const int lane = tid & 31, wid = tid >> 5;
    const int g = lane >> 2, tig = lane & 3;
    const int b = blockIdx.y / HEADS, h = blockIdx.y % HEADS;
    const int q0 = blockIdx.x * 128;
    const int qb = wid * 16;                   // this warp's local q-row base

    // ---- stage Q (prescaled) through Ps, then lift A-fragments to registers
    {
        const float* qg = Qp + ((size_t)(b * SEQ + q0)) * DMODEL + h * DK;
        #pragma unroll
        for (int i = 0; i < 8; i++) {
            const int L = tid + i * 256;
            const int r = L >> 4, c = (L & 15) * 4;
            float4 v = *(const float4*)(qg + (size_t)r * DMODEL + c);
            v.x *= 0.125f; v.y *= 0.125f; v.z *= 0.125f; v.w *= 0.125f;
            st_tf4(Ps + r * ALD + c, v);
        }
    }
    __syncthreads();

    uint32_t qf[8][4];
    #pragma unroll
    for (int ks = 0; ks < 8; ks++) {
        const int kk = ks * 8;
        qf[ks][0] = Ps[(qb + g) * ALD + kk + tig];
        qf[ks][1] = Ps[(qb + 8 + g) * ALD + kk + tig];
        qf[ks][2] = Ps[(qb + g) * ALD + kk + tig + 4];
        qf[ks][3] = Ps[(qb + 8 + g) * ALD + kk + tig + 4];
    }
    __syncthreads();

    float o[8][4] = {};
    float l0 = 0.f, l1 = 0.f;

    const float* kg = Kp + ((size_t)b * SEQ) * DMODEL + h * DK;
    const float* vg = Vt + ((size_t)(b * DMODEL + h * DK)) * SEQ;
    const int* mg = mask + b * SEQ;

    for (int kt = 0; kt < SEQ / 64; kt++) {
        const int k0 = kt * 64;
        if (kt) __syncthreads();       // prior phases done with Ks/Vs/Ps

        // ---- stage K [key][d] and V [d][key], coalesced float4 ----
        #pragma unroll
        for (int i = 0; i < 4; i++) {
            const int L = tid + i * 256;
            const int r = L >> 4, c = (L & 15) * 4;
            float4 kv = *(const float4*)(kg + (size_t)(k0 + r) * DMODEL + c);
            st_tf4(Ks + r * ALD + c, kv);
            float4 vv = *(const float4*)(vg + (size_t)r * SEQ + k0 + c);
            st_tf4(Vs + r * ALD + c, vv);
        }
        if (tid < 64) Msf[tid] = (mg[k0 + tid] != 0) ? 1.f : 0.f;
        __syncthreads();

        // ---- S = Q K^T  (A from registers) ----
        float s[8][4] = {};
        #pragma unroll
        for (int ks = 0; ks < 8; ks++) {
            const int kk = ks * 8;
            #pragma unroll
            for (int j = 0; j < 8; j++) {
                const int cn = j * 8 + g;
                uint32_t b0 = Ks[cn * ALD + kk + tig];
                uint32_t b1 = Ks[cn * ALD + kk + tig + 4];
                mma8(s[j], qf[ks][0], qf[ks][1], qf[ks][2], qf[ks][3], b0, b1);
            }
        }

        // ---- softmax (no max subtraction), stage P rows to smem ----
        #pragma unroll
        for (int j = 0; j < 8; j++) {
            const int col = j * 8 + 2 * tig;
            float2 m = *(const float2*)&Msf[col];
            float p0 = __expf(s[j][0]) * m.x;
            float p1 = __expf(s[j][1]) * m.y;
            float p2 = __expf(s[j][2]) * m.x;
            float p3 = __expf(s[j][3]) * m.y;
            l0 += p0 + p1;
            l1 += p2 + p3;
            uint32_t* pr0 = Ps + (qb + g) * ALD + col;
            pr0[0] = f2tf(p0); pr0[1] = f2tf(p1);
            uint32_t* pr1 = Ps + (qb + 8 + g) * ALD + col;
            pr1[0] = f2tf(p2); pr1[1] = f2tf(p3);
        }
        __syncwarp();   // P rows are private to this warp

        // ---- O += P V^T ----
        #pragma unroll
        for (int ks = 0; ks < 8; ks++) {
            const int kk = ks * 8;
            uint32_t a0 = Ps[(qb + g) * ALD + kk + tig];
            uint32_t a1 = Ps[(qb + 8 + g) * ALD + kk + tig];
            uint32_t a2 = Ps[(qb + g) * ALD + kk + tig + 4];
            uint32_t a3 = Ps[(qb + 8 + g) * ALD + kk + tig + 4];
            #pragma unroll
            for (int j = 0; j < 8; j++) {
                const int dn = j * 8 + g;
                uint32_t b0 = Vs[dn * ALD + kk + tig];
                uint32_t b1 = Vs[dn * ALD + kk + tig + 4];
                mma8(o[j], a0, a1, a2, a3, b0, b1);
            }
        }
    }

    // ---- finalize: row sums across the 4-lane groups, write O ----
    l0 += __shfl_xor_sync(0xffffffffu, l0, 1);
    l0 += __shfl_xor_sync(0xffffffffu, l0, 2);
    l1 += __shfl_xor_sync(0xffffffffu, l1, 1);
    l1 += __shfl_xor_sync(0xffffffffu, l1, 2);
    const float i0 = 1.f / l0, i1 = 1.f / l1;

    float* cg = Ctx + ((size_t)(b * SEQ + q0 + qb)) * DMODEL + h * DK;
    #pragma unroll
    for (int j = 0; j < 8; j++) {
        const int col = j * 8 + 2 * tig;
        *(float2*)(cg + (size_t)g * DMODEL + col) =
            make_float2(o[j][0] * i0, o[j][1] * i0);
        *(float2*)(cg + (size_t)(8 + g) * DMODEL + col) =
            make_float2(o[j][2] * i1, o[j][3] * i1);
    }
}

// ---------------------------------------------------------------------------
// Launcher.  Inputs: q, k, v, Wq, bq, Wk, bk, Wv, bv, Wo, bo, mask
// ---------------------------------------------------------------------------
extern "C" void kernel_launch(void* const* d_in, const int* in_sizes, int n_in,
                              void* d_out, int out_size)
{
    const float* q    = (const float*)d_in[0];
    const float* k    = (const float*)d_in[1];
    const float* v    = (const float*)d_in[2];
    const float* Wq   = (const float*)d_in[3];
    const float* bq   = (const float*)d_in[4];
    const float* Wk   = (const float*)d_in[5];
    const float* bk   = (const float*)d_in[6];
    const float* Wv   = (const float*)d_in[7];
    const float* bv   = (const float*)d_in[8];
    const float* Wo   = (const float*)d_in[9];
    const float* bo   = (const float*)d_in[10];
    const int*   mask = (const int*)d_in[11];
    float* out = (float*)d_out;

    float *Qp, *Kp, *Vt, *Ctx;
    cudaGetSymbolAddress((void**)&Qp,  g_Qp);
    cudaGetSymbolAddress((void**)&Kp,  g_Kp);
    cudaGetSymbolAddress((void**)&Vt,  g_Vt);
    cudaGetSymbolAddress((void**)&Ctx, g_Ctx);

    cudaFuncSetAttribute(attn_tc, cudaFuncAttributeMaxDynamicSharedMemorySize,
                         ATT_SMEM);

    dim3 ggrid(DMODEL / GBN, MROWS / GBM);   // (6, 64)
    dim3 gblk(256);

    gemm_tc<0><<<ggrid, gblk>>>(q, Wq, bq, Qp, MROWS, DMODEL, DMODEL);
    gemm_tc<0><<<ggrid, gblk>>>(k, Wk, bk, Kp, MROWS, DMODEL, DMODEL);
    gemm_tc<1><<<ggrid, gblk>>>(v, Wv, bv, Vt, MROWS, DMODEL, DMODEL);

    dim3 agrid(SEQ / 128, BS * HEADS);       // (32, 24)
    attn_tc<<<agrid, 256, ATT_SMEM>>>(Qp, Kp, Vt, mask, Ctx);

    gemm_tc<0><<<ggrid, gblk>>>(Ctx, Wo, bo, out, MROWS, DMODEL, DMODEL);
}

// round 6
// speedup vs baseline: 2.5030x; 1.9238x over previous
#include <cuda_runtime.h>
#include <cuda_fp16.h>
#include <cstdint>

// ---------------------------------------------------------------------------
// Problem constants
// ---------------------------------------------------------------------------
#define BS      2
#define SEQ     4096
#define DMODEL  768
#define HEADS   12
#define DK      64
#define MROWS   (BS * SEQ)          // 8192

// ---------------------------------------------------------------------------
// Scratch (device globals; no cudaMalloc allowed)
// ---------------------------------------------------------------------------
__device__ float g_Qp[MROWS * DMODEL];
__device__ float g_Kp[MROWS * DMODEL];
__device__ float g_Vt[(size_t)BS * DMODEL * SEQ];   // [b][dmodel][seq]
__device__ float g_Ctx[MROWS * DMODEL];

// ---------------------------------------------------------------------------
// Helpers: fp16 convert + mma.sync m16n8k16
// ---------------------------------------------------------------------------
__device__ __forceinline__ void mma16(float* d, const uint32_t* a,
                                      uint32_t b0, uint32_t b1) {
    asm volatile(
        "mma.sync.aligned.m16n8k16.row.col.f32.f16.f16.f32 "
        "{%0,%1,%2,%3}, {%4,%5,%6,%7}, {%8,%9}, {%0,%1,%2,%3};"
        : "+f"(d[0]), "+f"(d[1]), "+f"(d[2]), "+f"(d[3])
        : "r"(a[0]), "r"(a[1]), "r"(a[2]), "r"(a[3]), "r"(b0), "r"(b1));
}

__device__ __forceinline__ uint32_t packh2(float a, float b) {
    __half2 h = __floats2half2_rn(a, b);
    return *(uint32_t*)&h;
}

// store float4 -> 4 contiguous halves (8B)
__device__ __forceinline__ void st_h4(__half* p, float4 v) {
    uint2 u;
    u.x = packh2(v.x, v.y);
    u.y = packh2(v.z, v.w);
    *(uint2*)p = u;
}

// ---------------------------------------------------------------------------
// GEMM: C[M,N] = A[M,K] @ B[N,K]^T + bias[N]  via fp16 mma.sync, fp32 accum.
// 128x128 tile, BK=32, 256 threads = 8 warps (4m x 2n), warp tile 32x64.
// Smem rows padded to 40 halves (80B): fragment reads conflict-free.
// TRANS=1: write C transposed per batch into Vt[(b*DMODEL+n)*SEQ + s].
// ---------------------------------------------------------------------------
#define GBM 128
#define GBN 128
#define GBK 32
#define GLDH 40     // halves per smem row

template <int TRANS>
__global__ __launch_bounds__(256, 2) void gemm_tc(
    const float* __restrict__ A, const float* __restrict__ B,
    const float* __restrict__ bias, float* __restrict__ C,
    int M, int N, int K)
{
    __shared__ __half As[GBM * GLDH];
    __shared__ __half Bs[GBN * GLDH];

    const int tid = threadIdx.x;
    const int lane = tid & 31, wid = tid >> 5;
    const int g = lane >> 2, tig = lane & 3;
    const int wm = (wid & 3) * 32, wn = (wid >> 2) * 64;
    const int row0 = blockIdx.y * GBM, col0 = blockIdx.x * GBN;

    const int r = tid >> 3;            // 0..31
    const int c4 = (tid & 7) * 4;      // 0,4,...,28
    const float* Aptr = A + (size_t)(row0 + r) * K + c4;
    const float* Bptr = B + (size_t)(col0 + r) * K + c4;

    float4 pa[4], pb[4];
    #pragma unroll
    for (int m = 0; m < 4; m++) {
        pa[m] = *(const float4*)(Aptr + (size_t)(32 * m) * K);
        pb[m] = *(const float4*)(Bptr + (size_t)(32 * m) * K);
    }

    float acc[2][8][4] = {};

    int k0 = 0;
    while (true) {
        __syncthreads();
        #pragma unroll
        for (int m = 0; m < 4; m++) {
            st_h4(As + (r + 32 * m) * GLDH + c4, pa[m]);
            st_h4(Bs + (r + 32 * m) * GLDH + c4, pb[m]);
        }
        __syncthreads();

        k0 += GBK;
        const bool more = (k0 < K);
        if (more) {
            #pragma unroll
            for (int m = 0; m < 4; m++) {
                pa[m] = *(const float4*)(Aptr + (size_t)(32 * m) * K + k0);
                pb[m] = *(const float4*)(Bptr + (size_t)(32 * m) * K + k0);
            }
        }

        #pragma unroll
        for (int c = 0; c < 2; c++) {
            const int kk = 16 * c + 2 * tig;
            uint32_t a[2][4];
            #pragma unroll
            for (int i = 0; i < 2; i++) {
                const int rb = wm + 16 * i;
                a[i][0] = *(const uint32_t*)&As[(rb + g) * GLDH + kk];
                a[i][1] = *(const uint32_t*)&As[(rb + 8 + g) * GLDH + kk];
                a[i][2] = *(const uint32_t*)&As[(rb + g) * GLDH + kk + 8];
                a[i][3] = *(const uint32_t*)&As[(rb + 8 + g) * GLDH + kk + 8];
            }
            #pragma unroll
            for (int j = 0; j < 8; j++) {
                const int cn = wn + j * 8 + g;
                uint32_t b0 = *(const uint32_t*)&Bs[cn * GLDH + kk];
                uint32_t b1 = *(const uint32_t*)&Bs[cn * GLDH + kk + 8];
                mma16(acc[0][j], a[0], b0, b1);
                mma16(acc[1][j], a[1], b0, b1);
            }
        }
        if (!more) break;
    }

    #pragma unroll
    for (int i = 0; i < 2; i++) {
        const int rA = row0 + wm + i * 16 + g;
        const int rB = rA + 8;
        #pragma unroll
        for (int j = 0; j < 8; j++) {
            const int col = col0 + wn + j * 8 + 2 * tig;
            const float bx = __ldg(bias + col), by = __ldg(bias + col + 1);
            if (TRANS == 0) {
                float2 v0 = make_float2(acc[i][j][0] + bx, acc[i][j][1] + by);
                float2 v1 = make_float2(acc[i][j][2] + bx, acc[i][j][3] + by);
                *(float2*)(C + (size_t)rA * N + col) = v0;
                *(float2*)(C + (size_t)rB * N + col) = v1;
            } else {
                const int bA = rA >> 12, sA = rA & (SEQ - 1);
                const int bB = rB >> 12, sB = rB & (SEQ - 1);
                C[((size_t)bA * DMODEL + col)     * SEQ + sA] = acc[i][j][0] + bx;
                C[((size_t)bA * DMODEL + col + 1) * SEQ + sA] = acc[i][j][1] + by;
                C[((size_t)bB * DMODEL + col)     * SEQ + sB] = acc[i][j][2] + bx;
                C[((size_t)bB * DMODEL + col + 1) * SEQ + sB] = acc[i][j][3] + by;
            }
        }
    }
}

// ---------------------------------------------------------------------------
// Attention, fp16 mma m16n8k16.
// CTA = (b, h, 128-query tile), 256 threads = 8 warps x 16 q-rows.
// Smem: Ks[64 keys][72 halves], Vs[64 d][72 halves] (V as [d][key]).
// Q staged once through the K/V region (exactly 128x72), A-frags -> 16 regs.
// S C-fragments are exp()'d and repacked IN REGISTERS as the A-fragments of
// the O-mma (the m16n8 C layout matches the m16n8k16 A layout) -> P never
// touches smem. Row stride 144B => all fragment accesses conflict-free.
// ---------------------------------------------------------------------------
#define KLD 72

__global__ void __launch_bounds__(256, 2)
attn_tc(const float* __restrict__ Qp, const float* __restrict__ Kp,
        const float* __restrict__ Vt, const int* __restrict__ mask,
        float* __restrict__ Ctx)
{
    __shared__ __half KV[2 * 64 * KLD];   // doubles as Q staging [128][KLD]
    __shared__ float Msf[64];
    __half* Ks = KV;
    __half* Vs = KV + 64 * KLD;

    const int tid = threadIdx.x;
    const int lane = tid & 31, wid = tid >> 5;
    const int g = lane >> 2, tig = lane & 3;
    const int b = blockIdx.y / HEADS, h = blockIdx.y % HEADS;
    const int q0 = blockIdx.x * 128;
    const int qb = wid * 16;

    // ---- stage Q (prescaled 1/8) through KV region, lift A-frags to regs --
    {
        const float* qg = Qp + ((size_t)(b * SEQ + q0)) * DMODEL + h * DK;
        #pragma unroll
        for (int i = 0; i < 8; i++) {
            const int L = tid + i * 256;
            const int r = L >> 4, c4 = (L & 15) * 4;
            float4 v = *(const float4*)(qg + (size_t)r * DMODEL + c4);
            v.x *= 0.125f; v.y *= 0.125f; v.z *= 0.125f; v.w *= 0.125f;
            st_h4(KV + r * KLD + c4, v);
        }
    }
    __syncthreads();

    uint32_t qf[4][4];
    #pragma unroll
    for (int c = 0; c < 4; c++) {
        const int kk = 16 * c + 2 * tig;
        qf[c][0] = *(const uint32_t*)&KV[(qb + g) * KLD + kk];
        qf[c][1] = *(const uint32_t*)&KV[(qb + 8 + g) * KLD + kk];
        qf[c][2] = *(const uint32_t*)&KV[(qb + g) * KLD + kk + 8];
        qf[c][3] = *(const uint32_t*)&KV[(qb + 8 + g) * KLD + kk + 8];
    }
    __syncthreads();

    float o[8][4] = {};
    float l0 = 0.f, l1 = 0.f;

    const float* kg = Kp + ((size_t)b * SEQ) * DMODEL + h * DK;
    const float* vg = Vt + ((size_t)(b * DMODEL + h * DK)) * SEQ;
    const int* mg = mask + b * SEQ;

    for (int kt = 0; kt < SEQ / 64; kt++) {
        const int k0 = kt * 64;
        if (kt) __syncthreads();     // all warps done with Ks/Vs of prev tile

        // ---- stage K [key][d] and V [d][key], coalesced float4 -> fp16 ----
        #pragma unroll
        for (int i = 0; i < 4; i++) {
            const int L = tid + i * 256;
            const int r = L >> 4, c4 = (L & 15) * 4;
            float4 kv = *(const float4*)(kg + (size_t)(k0 + r) * DMODEL + c4);
            st_h4(Ks + r * KLD + c4, kv);
            float4 vv = *(const float4*)(vg + (size_t)r * SEQ + k0 + c4);
            st_h4(Vs + r * KLD + c4, vv);
        }
        if (tid < 64) Msf[tid] = (mg[k0 + tid] != 0) ? 1.f : 0.f;
        __syncthreads();

        // ---- S = Q K^T  (A from registers) ----
        float s[8][4] = {};
        #pragma unroll
        for (int c = 0; c < 4; c++) {
            const int kk = 16 * c + 2 * tig;
            #pragma unroll
            for (int j = 0; j < 8; j++) {
                const int rn = (j * 8 + g) * KLD + kk;
                uint32_t b0 = *(const uint32_t*)&Ks[rn];
                uint32_t b1 = *(const uint32_t*)&Ks[rn + 8];
                mma16(s[j], qf[c], b0, b1);
            }
        }

        // ---- softmax; repack P in registers as O-mma A-fragments ----
        uint32_t pa[8][2];
        #pragma unroll
        for (int j = 0; j < 8; j++) {
            float2 m = *(const float2*)&Msf[j * 8 + 2 * tig];
            float p0 = __expf(s[j][0]) * m.x;
            float p1 = __expf(s[j][1]) * m.y;
            float p2 = __expf(s[j][2]) * m.x;
            float p3 = __expf(s[j][3]) * m.y;
            l0 += p0 + p1;
            l1 += p2 + p3;
            pa[j][0] = packh2(p0, p1);   // row g,   keys 8j+2tig, +1
            pa[j][1] = packh2(p2, p3);   // row g+8
        }

        // ---- O += P V^T ----
        #pragma unroll
        for (int m = 0; m < 4; m++) {
            uint32_t av[4] = { pa[2 * m][0], pa[2 * m][1],
                               pa[2 * m + 1][0], pa[2 * m + 1][1] };
            const int kk = 16 * m + 2 * tig;
            #pragma unroll
            for (int j = 0; j < 8; j++) {
                const int rn = (j * 8 + g) * KLD + kk;
                uint32_t b0 = *(const uint32_t*)&Vs[rn];
                uint32_t b1 = *(const uint32_t*)&Vs[rn + 8];
                mma16(o[j], av, b0, b1);
            }
        }
    }

    // ---- finalize: row sums across the 4-lane groups, write O ----
    l0 += __shfl_xor_sync(0xffffffffu, l0, 1);
    l0 += __shfl_xor_sync(0xffffffffu, l0, 2);
    l1 += __shfl_xor_sync(0xffffffffu, l1, 1);
    l1 += __shfl_xor_sync(0xffffffffu, l1, 2);
    const float i0 = 1.f / l0, i1 = 1.f / l1;

    float* cg = Ctx + ((size_t)(b * SEQ + q0 + qb)) * DMODEL + h * DK;
    #pragma unroll
    for (int j = 0; j < 8; j++) {
        const int col = j * 8 + 2 * tig;
        *(float2*)(cg + (size_t)g * DMODEL + col) =
            make_float2(o[j][0] * i0, o[j][1] * i0);
        *(float2*)(cg + (size_t)(8 + g) * DMODEL + col) =
            make_float2(o[j][2] * i1, o[j][3] * i1);
    }
}

// ---------------------------------------------------------------------------
// Launcher.  Inputs: q, k, v, Wq, bq, Wk, bk, Wv, bv, Wo, bo, mask
// ---------------------------------------------------------------------------
extern "C" void kernel_launch(void* const* d_in, const int* in_sizes, int n_in,
                              void* d_out, int out_size)
{
    const float* q    = (const float*)d_in[0];
    const float* k    = (const float*)d_in[1];
    const float* v    = (const float*)d_in[2];
    const float* Wq   = (const float*)d_in[3];
    const float* bq   = (const float*)d_in[4];
    const float* Wk   = (const float*)d_in[5];
    const float* bk   = (const float*)d_in[6];
    const float* Wv   = (const float*)d_in[7];
    const float* bv   = (const float*)d_in[8];
    const float* Wo   = (const float*)d_in[9];
    const float* bo   = (const float*)d_in[10];
    const int*   mask = (const int*)d_in[11];
    float* out = (float*)d_out;

    float *Qp, *Kp, *Vt, *Ctx;
    cudaGetSymbolAddress((void**)&Qp,  g_Qp);
    cudaGetSymbolAddress((void**)&Kp,  g_Kp);
    cudaGetSymbolAddress((void**)&Vt,  g_Vt);
    cudaGetSymbolAddress((void**)&Ctx, g_Ctx);

    dim3 ggrid(DMODEL / GBN, MROWS / GBM);   // (6, 64)
    dim3 gblk(256);

    gemm_tc<0><<<ggrid, gblk>>>(q, Wq, bq, Qp, MROWS, DMODEL, DMODEL);
    gemm_tc<0><<<ggrid, gblk>>>(k, Wk, bk, Kp, MROWS, DMODEL, DMODEL);
    gemm_tc<1><<<ggrid, gblk>>>(v, Wv, bv, Vt, MROWS, DMODEL, DMODEL);

    dim3 agrid(SEQ / 128, BS * HEADS);       // (32, 24)
    attn_tc<<<agrid, 256>>>(Qp, Kp, Vt, mask, Ctx);

    gemm_tc<0><<<ggrid, gblk>>>(Ctx, Wo, bo, out, MROWS, DMODEL, DMODEL);
}

// round 7
// speedup vs baseline: 2.5752x; 1.0288x over previous
#include <cuda_runtime.h>
#include <cuda_fp16.h>
#include <cstdint>

// ---------------------------------------------------------------------------
// Problem constants
// ---------------------------------------------------------------------------
#define BS      2
#define SEQ     4096
#define DMODEL  768
#define HEADS   12
#define DK      64
#define MROWS   (BS * SEQ)          // 8192

// ---------------------------------------------------------------------------
// Scratch (device globals; no cudaMalloc allowed)
// ---------------------------------------------------------------------------
__device__ __half g_Qp[MROWS * DMODEL];              // prescaled by 1/8
__device__ __half g_Kp[MROWS * DMODEL];
__device__ __half g_Vt[(size_t)BS * DMODEL * SEQ];   // [b][dmodel][seq]
__device__ float  g_Ctx[MROWS * DMODEL];

// ---------------------------------------------------------------------------
// Helpers
// ---------------------------------------------------------------------------
__device__ __forceinline__ void mma16(float* d, const uint32_t* a,
                                      uint32_t b0, uint32_t b1) {
    asm volatile(
        "mma.sync.aligned.m16n8k16.row.col.f32.f16.f16.f32 "
        "{%0,%1,%2,%3}, {%4,%5,%6,%7}, {%8,%9}, {%0,%1,%2,%3};"
        : "+f"(d[0]), "+f"(d[1]), "+f"(d[2]), "+f"(d[3])
        : "r"(a[0]), "r"(a[1]), "r"(a[2]), "r"(a[3]), "r"(b0), "r"(b1));
}

__device__ __forceinline__ uint32_t packh2(float a, float b) {
    __half2 h = __floats2half2_rn(a, b);
    return *(uint32_t*)&h;
}

__device__ __forceinline__ void st_h4(__half* p, float4 v) {
    uint2 u;
    u.x = packh2(v.x, v.y);
    u.y = packh2(v.z, v.w);
    *(uint2*)p = u;
}

// ---------------------------------------------------------------------------
// GEMM: C[M,N] = (A[M,K] @ B[N,K]^T + bias[N]) * scale   via fp16 mma.sync.
// 128x128 tile, BK=32, 256 threads = 8 warps (4m x 2n), warp tile 32x64.
// OutT in {float, __half}. TRANS=1: write transposed per batch (Vt layout).
// ---------------------------------------------------------------------------
#define GBM 128
#define GBN 128
#define GBK 32
#define GLDH 40     // halves per smem row

template <typename OutT, int TRANS>
__global__ __launch_bounds__(256, 2) void gemm_tc(
    const float* __restrict__ A, const float* __restrict__ B,
    const float* __restrict__ bias, OutT* __restrict__ C,
    int M, int N, int K, float scale)
{
    __shared__ __half As[GBM * GLDH];
    __shared__ __half Bs[GBN * GLDH];

    const int tid = threadIdx.x;
    const int lane = tid & 31, wid = tid >> 5;
    const int g = lane >> 2, tig = lane & 3;
    const int wm = (wid & 3) * 32, wn = (wid >> 2) * 64;
    const int row0 = blockIdx.y * GBM, col0 = blockIdx.x * GBN;

    const int r = tid >> 3;            // 0..31
    const int c4 = (tid & 7) * 4;      // 0,4,...,28
    const float* Aptr = A + (size_t)(row0 + r) * K + c4;
    const float* Bptr = B + (size_t)(col0 + r) * K + c4;

    float4 pa[4], pb[4];
    #pragma unroll
    for (int m = 0; m < 4; m++) {
        pa[m] = *(const float4*)(Aptr + (size_t)(32 * m) * K);
        pb[m] = *(const float4*)(Bptr + (size_t)(32 * m) * K);
    }

    float acc[2][8][4] = {};

    int k0 = 0;
    while (true) {
        __syncthreads();
        #pragma unroll
        for (int m = 0; m < 4; m++) {
            st_h4(As + (r + 32 * m) * GLDH + c4, pa[m]);
            st_h4(Bs + (r + 32 * m) * GLDH + c4, pb[m]);
        }
        __syncthreads();

        k0 += GBK;
        const bool more = (k0 < K);
        if (more) {
            #pragma unroll
            for (int m = 0; m < 4; m++) {
                pa[m] = *(const float4*)(Aptr + (size_t)(32 * m) * K + k0);
                pb[m] = *(const float4*)(Bptr + (size_t)(32 * m) * K + k0);
            }
        }

        #pragma unroll
        for (int c = 0; c < 2; c++) {
            const int kk = 16 * c + 2 * tig;
            uint32_t a[2][4];
            #pragma unroll
            for (int i = 0; i < 2; i++) {
                const int rb = wm + 16 * i;
                a[i][0] = *(const uint32_t*)&As[(rb + g) * GLDH + kk];
                a[i][1] = *(const uint32_t*)&As[(rb + 8 + g) * GLDH + kk];
                a[i][2] = *(const uint32_t*)&As[(rb + g) * GLDH + kk + 8];
                a[i][3] = *(const uint32_t*)&As[(rb + 8 + g) * GLDH + kk + 8];
            }
            #pragma unroll
            for (int j = 0; j < 8; j++) {
                const int cn = wn + j * 8 + g;
                uint32_t b0 = *(const uint32_t*)&Bs[cn * GLDH + kk];
                uint32_t b1 = *(const uint32_t*)&Bs[cn * GLDH + kk + 8];
                mma16(acc[0][j], a[0], b0, b1);
                mma16(acc[1][j], a[1], b0, b1);
            }
        }
        if (!more) break;
    }

    #pragma unroll
    for (int i = 0; i < 2; i++) {
        const int rA = row0 + wm + i * 16 + g;
        const int rB = rA + 8;
        #pragma unroll
        for (int j = 0; j < 8; j++) {
            const int col = col0 + wn + j * 8 + 2 * tig;
            const float bx = __ldg(bias + col), by = __ldg(bias + col + 1);
            const float v0 = (acc[i][j][0] + bx) * scale;
            const float v1 = (acc[i][j][1] + by) * scale;
            const float v2 = (acc[i][j][2] + bx) * scale;
            const float v3 = (acc[i][j][3] + by) * scale;
            if (TRANS == 0) {
                if (sizeof(OutT) == 2) {
                    __half2* pA = (__half2*)((__half*)C + (size_t)rA * N + col);
                    __half2* pB = (__half2*)((__half*)C + (size_t)rB * N + col);
                    *pA = __floats2half2_rn(v0, v1);
                    *pB = __floats2half2_rn(v2, v3);
                } else {
                    *(float2*)((float*)C + (size_t)rA * N + col) = make_float2(v0, v1);
                    *(float2*)((float*)C + (size_t)rB * N + col) = make_float2(v2, v3);
                }
            } else {
                const int bA = rA >> 12, sA = rA & (SEQ - 1);
                const int bB = rB >> 12, sB = rB & (SEQ - 1);
                C[((size_t)bA * DMODEL + col)     * SEQ + sA] = (OutT)v0;
                C[((size_t)bA * DMODEL + col + 1) * SEQ + sA] = (OutT)v1;
                C[((size_t)bB * DMODEL + col)     * SEQ + sB] = (OutT)v2;
                C[((size_t)bB * DMODEL + col + 1) * SEQ + sB] = (OutT)v3;
            }
        }
    }
}

// ---------------------------------------------------------------------------
// Attention, fp16 mma m16n8k16 with 32-query warp tiles (B-fragment reuse x2).
// CTA = (b, h, 128-query tile), 128 threads = 4 warps x 32 q-rows.
// Smem: Ks[64 keys][KLD], Vs[64 d][KLD] halves; Q staged once through it.
// All inputs already fp16 (Q prescaled by 1/8 in its projection GEMM):
// staging is pure uint4 copy. P stays in registers (C-frag == A-frag layout).
// Row stride KLD=72 halves (144B): fragment LDS conflict-free (36w % 32 = 4).
// ---------------------------------------------------------------------------
#define KLD 72

__global__ void __launch_bounds__(128)
attn_tc(const __half* __restrict__ Qp, const __half* __restrict__ Kp,
        const __half* __restrict__ Vt, const int* __restrict__ mask,
        float* __restrict__ Ctx)
{
    __shared__ __half KV[2 * 64 * KLD];   // doubles as Q staging [128][KLD]
    __shared__ float Msf[64];
    __half* Ks = KV;
    __half* Vs = KV + 64 * KLD;

    const int tid = threadIdx.x;
    const int lane = tid & 31, wid = tid >> 5;     // wid 0..3
    const int g = lane >> 2, tig = lane & 3;
    const int b = blockIdx.y / HEADS, h = blockIdx.y % HEADS;
    const int q0 = blockIdx.x * 128;
    const int qb = wid * 32;                        // warp's 32 q-rows

    // ---- stage Q (fp16, pre-scaled) through KV region ----
    {
        const __half* qg = Qp + ((size_t)(b * SEQ + q0)) * DMODEL + h * DK;
        #pragma unroll
        for (int i = 0; i < 8; i++) {
            const int L = tid + i * 128;
            const int r = L >> 3, c8 = (L & 7) * 8;
            *(uint4*)(KV + r * KLD + c8) =
                *(const uint4*)(qg + (size_t)r * DMODEL + c8);
        }
    }
    __syncthreads();

    // ---- lift Q A-fragments for 32 rows to registers (2 x 16-row tiles) ----
    uint32_t qf[4][2][4];
    #pragma unroll
    for (int c = 0; c < 4; c++) {
        const int kk = 16 * c + 2 * tig;
        #pragma unroll
        for (int i = 0; i < 2; i++) {
            const int rb = qb + 16 * i;
            qf[c][i][0] = *(const uint32_t*)&KV[(rb + g) * KLD + kk];
            qf[c][i][1] = *(const uint32_t*)&KV[(rb + 8 + g) * KLD + kk];
            qf[c][i][2] = *(const uint32_t*)&KV[(rb + g) * KLD + kk + 8];
            qf[c][i][3] = *(const uint32_t*)&KV[(rb + 8 + g) * KLD + kk + 8];
        }
    }
    __syncthreads();

    float o[2][8][4] = {};
    float l00 = 0.f, l01 = 0.f, l10 = 0.f, l11 = 0.f;

    const __half* kg = Kp + ((size_t)b * SEQ) * DMODEL + h * DK;
    const __half* vg = Vt + ((size_t)(b * DMODEL + h * DK)) * SEQ;
    const int* mg = mask + b * SEQ;

    for (int kt = 0; kt < SEQ / 64; kt++) {
        const int k0 = kt * 64;
        if (kt) __syncthreads();

        // ---- stage K [key][d] and V [d][key]: pure uint4 copies ----
        #pragma unroll
        for (int i = 0; i < 4; i++) {
            const int L = tid + i * 128;
            const int r = L >> 3, c8 = (L & 7) * 8;
            *(uint4*)(Ks + r * KLD + c8) =
                *(const uint4*)(kg + (size_t)(k0 + r) * DMODEL + c8);
            *(uint4*)(Vs + r * KLD + c8) =
                *(const uint4*)(vg + (size_t)r * SEQ + k0 + c8);
        }
        if (tid < 64) Msf[tid] = (mg[k0 + tid] != 0) ? 1.f : 0.f;
        __syncthreads();

        // ---- S = Q K^T : each B fragment feeds 2 mmas ----
        float s[2][8][4] = {};
        #pragma unroll
        for (int c = 0; c < 4; c++) {
            const int kk = 16 * c + 2 * tig;
            #pragma unroll
            for (int j = 0; j < 8; j++) {
                const int rn = (j * 8 + g) * KLD + kk;
                uint32_t b0 = *(const uint32_t*)&Ks[rn];
                uint32_t b1 = *(const uint32_t*)&Ks[rn + 8];
                mma16(s[0][j], qf[c][0], b0, b1);
                mma16(s[1][j], qf[c][1], b0, b1);
            }
        }

        // ---- softmax; repack P in registers as O-mma A-fragments ----
        uint32_t pa[2][8][2];
        #pragma unroll
        for (int j = 0; j < 8; j++) {
            float2 m = *(const float2*)&Msf[j * 8 + 2 * tig];
            {
                float p0 = __expf(s[0][j][0]) * m.x;
                float p1 = __expf(s[0][j][1]) * m.y;
                float p2 = __expf(s[0][j][2]) * m.x;
                float p3 = __expf(s[0][j][3]) * m.y;
                l00 += p0 + p1; l01 += p2 + p3;
                pa[0][j][0] = packh2(p0, p1);
                pa[0][j][1] = packh2(p2, p3);
            }
            {
                float p0 = __expf(s[1][j][0]) * m.x;
                float p1 = __expf(s[1][j][1]) * m.y;
                float p2 = __expf(s[1][j][2]) * m.x;
                float p3 = __expf(s[1][j][3]) * m.y;
                l10 += p0 + p1; l11 += p2 + p3;
                pa[1][j][0] = packh2(p0, p1);
                pa[1][j][1] = packh2(p2, p3);
            }
        }

        // ---- O += P V^T : each B fragment feeds 2 mmas ----
        #pragma unroll
        for (int m = 0; m < 4; m++) {
            uint32_t av0[4] = { pa[0][2 * m][0], pa[0][2 * m][1],
                                pa[0][2 * m + 1][0], pa[0][2 * m + 1][1] };
            uint32_t av1[4] = { pa[1][2 * m][0], pa[1][2 * m][1],
                                pa[1][2 * m + 1][0], pa[1][2 * m + 1][1] };
            const int kk = 16 * m + 2 * tig;
            #pragma unroll
            for (int j = 0; j < 8; j++) {
                const int rn = (j * 8 + g) * KLD + kk;
                uint32_t b0 = *(const uint32_t*)&Vs[rn];
                uint32_t b1 = *(const uint32_t*)&Vs[rn + 8];
                mma16(o[0][j], av0, b0, b1);
                mma16(o[1][j], av1, b0, b1);
            }
        }
    }

    // ---- finalize: reduce row sums across 4-lane groups, write O ----
    l00 += __shfl_xor_sync(0xffffffffu, l00, 1);
    l00 += __shfl_xor_sync(0xffffffffu, l00, 2);
    l01 += __shfl_xor_sync(0xffffffffu, l01, 1);
    l01 += __shfl_xor_sync(0xffffffffu, l01, 2);
    l10 += __shfl_xor_sync(0xffffffffu, l10, 1);
    l10 += __shfl_xor_sync(0xffffffffu, l10, 2);
    l11 += __shfl_xor_sync(0xffffffffu, l11, 1);
    l11 += __shfl_xor_sync(0xffffffffu, l11, 2);
    const float inv[2][2] = { {1.f / l00, 1.f / l01}, {1.f / l10, 1.f / l11} };

    #pragma unroll
    for (int i = 0; i < 2; i++) {
        float* cg = Ctx + ((size_t)(b * SEQ + q0 + qb + 16 * i)) * DMODEL + h * DK;
        #pragma unroll
        for (int j = 0; j < 8; j++) {
            const int col = j * 8 + 2 * tig;
            *(float2*)(cg + (size_t)g * DMODEL + col) =
                make_float2(o[i][j][0] * inv[i][0], o[i][j][1] * inv[i][0]);
            *(float2*)(cg + (size_t)(8 + g) * DMODEL + col) =
                make_float2(o[i][j][2] * inv[i][1], o[i][j][3] * inv[i][1]);
        }
    }
}

// ---------------------------------------------------------------------------
// Launcher.  Inputs: q, k, v, Wq, bq, Wk, bk, Wv, bv, Wo, bo, mask
// ---------------------------------------------------------------------------
extern "C" void kernel_launch(void* const* d_in, const int* in_sizes, int n_in,
                              void* d_out, int out_size)
{
    const float* q    = (const float*)d_in[0];
    const float* k    = (const float*)d_in[1];
    const float* v    = (const float*)d_in[2];
    const float* Wq   = (const float*)d_in[3];
    const float* bq   = (const float*)d_in[4];
    const float* Wk   = (const float*)d_in[5];
    const float* bk   = (const float*)d_in[6];
    const float* Wv   = (const float*)d_in[7];
    const float* bv   = (const float*)d_in[8];
    const float* Wo   = (const float*)d_in[9];
    const float* bo   = (const float*)d_in[10];
    const int*   mask = (const int*)d_in[11];
    float* out = (float*)d_out;

    __half *Qp, *Kp, *Vt;
    float *Ctx;
    cudaGetSymbolAddress((void**)&Qp,  g_Qp);
    cudaGetSymbolAddress((void**)&Kp,  g_Kp);
    cudaGetSymbolAddress((void**)&Vt,  g_Vt);
    cudaGetSymbolAddress((void**)&Ctx, g_Ctx);

    dim3 ggrid(DMODEL / GBN, MROWS / GBM);   // (6, 64)
    dim3 gblk(256);

    gemm_tc<__half, 0><<<ggrid, gblk>>>(q, Wq, bq, Qp, MROWS, DMODEL, DMODEL, 0.125f);
    gemm_tc<__half, 0><<<ggrid, gblk>>>(k, Wk, bk, Kp, MROWS, DMODEL, DMODEL, 1.0f);
    gemm_tc<__half, 1><<<ggrid, gblk>>>(v, Wv, bv, Vt, MROWS, DMODEL, DMODEL, 1.0f);

    dim3 agrid(SEQ / 128, BS * HEADS);       // (32, 24)
    attn_tc<<<agrid, 128>>>(Qp, Kp, Vt, mask, Ctx);

    gemm_tc<float, 0><<<ggrid, gblk>>>(Ctx, Wo, bo, out, MROWS, DMODEL, DMODEL, 1.0f);
}